// round 7
// baseline (speedup 1.0000x reference)
#include <cuda_runtime.h>

#define NN   20000
#define INCH 256
#define HEADS 8
#define HID  32
#define C1   256      // HEADS*HID
#define OUTC 40
#define E0   320000
#define ET   340000   // + self loops
#define NEG  0.2f
#define DEGCAP1 512
#define DEGCAP2 1024

// ---------------- scratch (device globals; no allocation allowed) ----------
__device__ float g_h1[NN * C1];        // x @ W1
__device__ float g_as1[NN * HEADS];
__device__ float g_ad1[NN * HEADS];
__device__ float g_e1[ET * HEADS];     // fallback only (deg > DEGCAP1)
__device__ float g_out1[NN * C1];      // elu(aggr + b1)
__device__ float g_h2[NN * OUTC];      // out1 @ W2
__device__ float g_as2[NN];
__device__ float g_ad2[NN];
__device__ float g_e2[ET];             // fallback only (deg > DEGCAP2)
__device__ int   g_deg[NN];
__device__ int   g_off[NN + 1];
__device__ int   g_cur[NN];
__device__ int   g_src[ET];            // CSR payload: src node per slot

// ---------------- helpers ---------------------------------------------------
__device__ __forceinline__ unsigned f2tf32(float f) {
    unsigned r;
    asm volatile("cvt.rna.tf32.f32 %0, %1;" : "=r"(r) : "f"(f));
    return r;
}
__device__ __forceinline__ void mma_tf32(float* c, const unsigned* a, unsigned b0, unsigned b1) {
    asm volatile(
        "mma.sync.aligned.m16n8k8.row.col.f32.tf32.tf32.f32 "
        "{%0,%1,%2,%3}, {%4,%5,%6,%7}, {%8,%9}, {%0,%1,%2,%3};"
        : "+f"(c[0]), "+f"(c[1]), "+f"(c[2]), "+f"(c[3])
        : "r"(a[0]), "r"(a[1]), "r"(a[2]), "r"(a[3]), "r"(b0), "r"(b1));
}
__device__ __forceinline__ float lrelu_exp(float v) {
    v = v > 0.f ? v : NEG * v;
    return __expf(v);
}

// ---------------- CSR build --------------------------------------------------
// self-loops are folded in here: every node starts with degree 1
__global__ void init_deg() {
    int i = blockIdx.x * blockDim.x + threadIdx.x;
    if (i < NN) g_deg[i] = 1;
}

// 4 edges per thread, int4 loads of dst (E0 % 4 == 0)
__global__ void deg_hist(const int* __restrict__ ei) {
    int e4 = (blockIdx.x * blockDim.x + threadIdx.x) * 4;
    if (e4 >= E0) return;
    int4 d = *reinterpret_cast<const int4*>(&ei[E0 + e4]);
    atomicAdd(&g_deg[d.x], 1);
    atomicAdd(&g_deg[d.y], 1);
    atomicAdd(&g_deg[d.z], 1);
    atomicAdd(&g_deg[d.w], 1);
}

// single-block exclusive scan over g_deg -> g_off, g_cur
__global__ __launch_bounds__(1024) void scan_kernel() {
    __shared__ int wsum[32];
    __shared__ int carry_s;
    int tid = threadIdx.x;
    int lane = tid & 31, wid = tid >> 5;
    if (tid == 0) carry_s = 0;
    __syncthreads();
    for (int base = 0; base < NN; base += 1024) {
        int idx = base + tid;
        int v = (idx < NN) ? g_deg[idx] : 0;
        int x = v;
#pragma unroll
        for (int o = 1; o < 32; o <<= 1) {
            int y = __shfl_up_sync(~0u, x, o);
            if (lane >= o) x += y;
        }
        if (lane == 31) wsum[wid] = x;
        __syncthreads();
        if (wid == 0) {
            int w = wsum[lane];
#pragma unroll
            for (int o = 1; o < 32; o <<= 1) {
                int y = __shfl_up_sync(~0u, w, o);
                if (lane >= o) w += y;
            }
            wsum[lane] = w;
        }
        __syncthreads();
        int incl = x + (wid ? wsum[wid - 1] : 0);
        int excl = carry_s + incl - v;
        if (idx < NN) { g_off[idx] = excl; g_cur[idx] = excl; }
        __syncthreads();
        if (tid == 0) carry_s += wsum[31];
        __syncthreads();
    }
    if (tid == 0) g_off[NN] = carry_s;
}

// 4 edges per thread (incl self-loop tail); independent atomic chains -> MLP 4
__global__ void fill_csr(const int* __restrict__ ei) {
    int e4 = (blockIdx.x * blockDim.x + threadIdx.x) * 4;
    if (e4 + 3 < E0) {
        int4 s = *reinterpret_cast<const int4*>(&ei[e4]);
        int4 d = *reinterpret_cast<const int4*>(&ei[E0 + e4]);
        int p0 = atomicAdd(&g_cur[d.x], 1);
        int p1 = atomicAdd(&g_cur[d.y], 1);
        int p2 = atomicAdd(&g_cur[d.z], 1);
        int p3 = atomicAdd(&g_cur[d.w], 1);
        g_src[p0] = s.x; g_src[p1] = s.y; g_src[p2] = s.z; g_src[p3] = s.w;
    } else {
#pragma unroll
        for (int j = 0; j < 4; j++) {
            int e = e4 + j;
            if (e >= ET) break;
            int s, d;
            if (e < E0) { s = ei[e]; d = ei[E0 + e]; } else { s = d = e - E0; }
            int pos = atomicAdd(&g_cur[d], 1);
            g_src[pos] = s;
        }
    }
}

// ---------------- GEMM1: h1 = x @ W1  (tf32 tensor cores) -------------------
__global__ __launch_bounds__(256) void gemm1_kernel(const float* __restrict__ x,
                                                    const float* __restrict__ W1) {
    __shared__ float As[128][36];
    __shared__ float Bs[32][136];
    int tid = threadIdx.x;
    int lane = tid & 31, wid = tid >> 5;
    int wm = wid & 3, wn = wid >> 2;
    int g = lane >> 2, tg = lane & 3;
    int m0 = blockIdx.y * 128, n0 = blockIdx.x * 128;

    float acc[2][8][4];
#pragma unroll
    for (int i = 0; i < 2; i++)
#pragma unroll
        for (int j = 0; j < 8; j++)
#pragma unroll
            for (int k = 0; k < 4; k++) acc[i][j][k] = 0.f;

    int a_r = tid >> 3;
    int a_c = (tid & 7) * 4;
    int b_r = tid >> 3;
    int b_c0 = tid & 7;

    for (int k0 = 0; k0 < INCH; k0 += 32) {
#pragma unroll
        for (int j = 0; j < 4; j++) {
            int r = a_r + 32 * j;
            int gm = m0 + r;
            float4 v = make_float4(0.f, 0.f, 0.f, 0.f);
            if (gm < NN) v = *reinterpret_cast<const float4*>(&x[(size_t)gm * INCH + k0 + a_c]);
            As[r][a_c + 0] = __uint_as_float(f2tf32(v.x));
            As[r][a_c + 1] = __uint_as_float(f2tf32(v.y));
            As[r][a_c + 2] = __uint_as_float(f2tf32(v.z));
            As[r][a_c + 3] = __uint_as_float(f2tf32(v.w));
        }
#pragma unroll
        for (int j = 0; j < 4; j++) {
            int c = (b_c0 + 8 * j) * 4;
            float4 v = *reinterpret_cast<const float4*>(&W1[(size_t)(k0 + b_r) * C1 + n0 + c]);
            Bs[b_r][c + 0] = __uint_as_float(f2tf32(v.x));
            Bs[b_r][c + 1] = __uint_as_float(f2tf32(v.y));
            Bs[b_r][c + 2] = __uint_as_float(f2tf32(v.z));
            Bs[b_r][c + 3] = __uint_as_float(f2tf32(v.w));
        }
        __syncthreads();
#pragma unroll
        for (int ks = 0; ks < 4; ks++) {
            int kk = ks * 8;
            unsigned a[2][4];
#pragma unroll
            for (int mi = 0; mi < 2; mi++) {
                int rb = wm * 32 + mi * 16 + g;
                a[mi][0] = __float_as_uint(As[rb][kk + tg]);
                a[mi][1] = __float_as_uint(As[rb + 8][kk + tg]);
                a[mi][2] = __float_as_uint(As[rb][kk + tg + 4]);
                a[mi][3] = __float_as_uint(As[rb + 8][kk + tg + 4]);
            }
#pragma unroll
            for (int nt = 0; nt < 8; nt++) {
                int col = wn * 64 + nt * 8 + g;
                unsigned b0 = __float_as_uint(Bs[kk + tg][col]);
                unsigned b1 = __float_as_uint(Bs[kk + tg + 4][col]);
                mma_tf32(acc[0][nt], a[0], b0, b1);
                mma_tf32(acc[1][nt], a[1], b0, b1);
            }
        }
        __syncthreads();
    }
#pragma unroll
    for (int mi = 0; mi < 2; mi++) {
        int r = m0 + wm * 32 + mi * 16 + g;
#pragma unroll
        for (int nt = 0; nt < 8; nt++) {
            int c = n0 + wn * 64 + nt * 8 + tg * 2;
            if (r < NN) {
                g_h1[(size_t)r * C1 + c]     = acc[mi][nt][0];
                g_h1[(size_t)r * C1 + c + 1] = acc[mi][nt][1];
            }
            if (r + 8 < NN) {
                g_h1[(size_t)(r + 8) * C1 + c]     = acc[mi][nt][2];
                g_h1[(size_t)(r + 8) * C1 + c + 1] = acc[mi][nt][3];
            }
        }
    }
}

// ---------------- alpha projections (layer 1) --------------------------------
__global__ void alpha1_kernel(const float* __restrict__ a_src, const float* __restrict__ a_dst) {
    int n = blockIdx.x;
    int t = threadIdx.x;
    int h = t >> 5, l = t & 31;
    float v = g_h1[n * C1 + t];
    float s = v * a_src[t];
    float d = v * a_dst[t];
#pragma unroll
    for (int o = 16; o; o >>= 1) {
        s += __shfl_xor_sync(~0u, s, o);
        d += __shfl_xor_sync(~0u, d, o);
    }
    if (l == 0) { g_as1[n * HEADS + h] = s; g_ad1[n * HEADS + h] = d; }
}

// ---------------- layer1 gather: exp + den + aggregate + bias + ELU ---------
__global__ __launch_bounds__(256) void gather1(const float* __restrict__ b1) {
    int d = blockIdx.x;
    int tid = threadIdx.x;
    int start = g_off[d];
    int deg = g_off[d + 1] - start;
    bool fits = (deg <= DEGCAP1);

    __shared__ float sden[HEADS];
    __shared__ float sad[HEADS];
    __shared__ int   ssrc[DEGCAP1];
    __shared__ float sex[DEGCAP1 * HEADS];
    if (tid < HEADS) { sden[tid] = 0.f; sad[tid] = g_ad1[d * HEADS + tid]; }
    __syncthreads();

    // pass1: one edge per thread; cache (src, exp) in smem
    for (int i = tid; i < deg; i += 256) {
        int s = g_src[start + i];
        float4 v0 = *reinterpret_cast<const float4*>(&g_as1[s * HEADS]);
        float4 v1 = *reinterpret_cast<const float4*>(&g_as1[s * HEADS + 4]);
        float e0 = lrelu_exp(v0.x + sad[0]);
        float e1 = lrelu_exp(v0.y + sad[1]);
        float e2 = lrelu_exp(v0.z + sad[2]);
        float e3 = lrelu_exp(v0.w + sad[3]);
        float e4 = lrelu_exp(v1.x + sad[4]);
        float e5 = lrelu_exp(v1.y + sad[5]);
        float e6 = lrelu_exp(v1.z + sad[6]);
        float e7 = lrelu_exp(v1.w + sad[7]);
        if (fits) {
            ssrc[i] = s;
            sex[i * HEADS + 0] = e0; sex[i * HEADS + 1] = e1;
            sex[i * HEADS + 2] = e2; sex[i * HEADS + 3] = e3;
            sex[i * HEADS + 4] = e4; sex[i * HEADS + 5] = e5;
            sex[i * HEADS + 6] = e6; sex[i * HEADS + 7] = e7;
        } else {
            size_t base = (size_t)(start + i) * HEADS;
            g_e1[base + 0] = e0; g_e1[base + 1] = e1;
            g_e1[base + 2] = e2; g_e1[base + 3] = e3;
            g_e1[base + 4] = e4; g_e1[base + 5] = e5;
            g_e1[base + 6] = e6; g_e1[base + 7] = e7;
        }
        atomicAdd(&sden[0], e0); atomicAdd(&sden[1], e1);
        atomicAdd(&sden[2], e2); atomicAdd(&sden[3], e3);
        atomicAdd(&sden[4], e4); atomicAdd(&sden[5], e5);
        atomicAdd(&sden[6], e6); atomicAdd(&sden[7], e7);
    }
    __syncthreads();

    // pass2: per-channel register accumulation, unroll 4 for MLP
    int ch = tid;
    int h = ch >> 5;
    float acc = 0.f;
    if (fits) {
        int i = 0;
        for (; i + 4 <= deg; i += 4) {
            int s0 = ssrc[i], s1 = ssrc[i + 1], s2 = ssrc[i + 2], s3 = ssrc[i + 3];
            float e0 = sex[(i + 0) * HEADS + h];
            float e1 = sex[(i + 1) * HEADS + h];
            float e2 = sex[(i + 2) * HEADS + h];
            float e3 = sex[(i + 3) * HEADS + h];
            float h0 = g_h1[(size_t)s0 * C1 + ch];
            float h1 = g_h1[(size_t)s1 * C1 + ch];
            float h2 = g_h1[(size_t)s2 * C1 + ch];
            float h3 = g_h1[(size_t)s3 * C1 + ch];
            acc += e0 * h0 + e1 * h1 + e2 * h2 + e3 * h3;
        }
        for (; i < deg; i++)
            acc += sex[i * HEADS + h] * g_h1[(size_t)ssrc[i] * C1 + ch];
    } else {
        for (int i = 0; i < deg; i++) {
            int s = g_src[start + i];
            acc += g_e1[(size_t)(start + i) * HEADS + h] * g_h1[(size_t)s * C1 + ch];
        }
    }
    float o = acc / (sden[h] + 1e-16f) + b1[ch];
    g_out1[(size_t)d * C1 + ch] = o > 0.f ? o : expm1f(o);
}

// ---------------- GEMM2: h2 = out1 @ W2, + fused alpha2 ---------------------
__global__ __launch_bounds__(256) void gemm2_kernel(const float* __restrict__ W2,
                                                    const float* __restrict__ a2s,
                                                    const float* __restrict__ a2d) {
    __shared__ float As[128][36];
    __shared__ float Bs[32][44];
    int tid = threadIdx.x;
    int lane = tid & 31, wid = tid >> 5;
    int g = lane >> 2, tg = lane & 3;
    int m0 = blockIdx.x * 128;

    float acc[5][4];
#pragma unroll
    for (int j = 0; j < 5; j++)
#pragma unroll
        for (int k = 0; k < 4; k++) acc[j][k] = 0.f;

    int a_r = tid >> 3;
    int a_c = (tid & 7) * 4;

    for (int k0 = 0; k0 < C1; k0 += 32) {
#pragma unroll
        for (int j = 0; j < 4; j++) {
            int r = a_r + 32 * j;
            int gm = m0 + r;
            float4 v = make_float4(0.f, 0.f, 0.f, 0.f);
            if (gm < NN) v = *reinterpret_cast<const float4*>(&g_out1[(size_t)gm * C1 + k0 + a_c]);
            As[r][a_c + 0] = __uint_as_float(f2tf32(v.x));
            As[r][a_c + 1] = __uint_as_float(f2tf32(v.y));
            As[r][a_c + 2] = __uint_as_float(f2tf32(v.z));
            As[r][a_c + 3] = __uint_as_float(f2tf32(v.w));
        }
        for (int idx = tid; idx < 32 * OUTC; idx += 256) {
            int r = idx / OUTC, c = idx % OUTC;
            Bs[r][c] = __uint_as_float(f2tf32(W2[(size_t)(k0 + r) * OUTC + c]));
        }
        __syncthreads();
#pragma unroll
        for (int ks = 0; ks < 4; ks++) {
            int kk = ks * 8;
            unsigned a[4];
            int rb = wid * 16 + g;
            a[0] = __float_as_uint(As[rb][kk + tg]);
            a[1] = __float_as_uint(As[rb + 8][kk + tg]);
            a[2] = __float_as_uint(As[rb][kk + tg + 4]);
            a[3] = __float_as_uint(As[rb + 8][kk + tg + 4]);
#pragma unroll
            for (int nt = 0; nt < 5; nt++) {
                int col = nt * 8 + g;
                unsigned b0 = __float_as_uint(Bs[kk + tg][col]);
                unsigned b1r = __float_as_uint(Bs[kk + tg + 4][col]);
                mma_tf32(acc[nt], a, b0, b1r);
            }
        }
        __syncthreads();
    }
    int rlo = m0 + wid * 16 + g;
    int rhi = rlo + 8;
    float s_lo = 0.f, s_hi = 0.f, d_lo = 0.f, d_hi = 0.f;
#pragma unroll
    for (int nt = 0; nt < 5; nt++) {
        int c = nt * 8 + tg * 2;
        float w0s = a2s[c], w1s = a2s[c + 1];
        float w0d = a2d[c], w1d = a2d[c + 1];
        if (rlo < NN) {
            g_h2[(size_t)rlo * OUTC + c]     = acc[nt][0];
            g_h2[(size_t)rlo * OUTC + c + 1] = acc[nt][1];
        }
        if (rhi < NN) {
            g_h2[(size_t)rhi * OUTC + c]     = acc[nt][2];
            g_h2[(size_t)rhi * OUTC + c + 1] = acc[nt][3];
        }
        s_lo += acc[nt][0] * w0s + acc[nt][1] * w1s;
        s_hi += acc[nt][2] * w0s + acc[nt][3] * w1s;
        d_lo += acc[nt][0] * w0d + acc[nt][1] * w1d;
        d_hi += acc[nt][2] * w0d + acc[nt][3] * w1d;
    }
#pragma unroll
    for (int o = 1; o <= 2; o <<= 1) {
        s_lo += __shfl_xor_sync(~0u, s_lo, o);
        s_hi += __shfl_xor_sync(~0u, s_hi, o);
        d_lo += __shfl_xor_sync(~0u, d_lo, o);
        d_hi += __shfl_xor_sync(~0u, d_hi, o);
    }
    if (tg == 0) {
        if (rlo < NN) { g_as2[rlo] = s_lo; g_ad2[rlo] = d_lo; }
        if (rhi < NN) { g_as2[rhi] = s_hi; g_ad2[rhi] = d_hi; }
    }
}

// ---------------- layer2 gather: exp + den + aggregate + bias + log_softmax --
__global__ __launch_bounds__(64) void gather2(const float* __restrict__ b2,
                                              float* __restrict__ out) {
    int d = blockIdx.x;
    int tid = threadIdx.x;
    int start = g_off[d];
    int deg = g_off[d + 1] - start;
    bool fits = (deg <= DEGCAP2);

    __shared__ float sden;
    __shared__ float svals[OUTC];
    __shared__ int   ssrc[DEGCAP2];
    __shared__ float sex[DEGCAP2];
    if (tid == 0) sden = 0.f;
    __syncthreads();

    float add = g_ad2[d];
    float part = 0.f;
    for (int i = tid; i < deg; i += 64) {
        int s = g_src[start + i];
        float ex = lrelu_exp(g_as2[s] + add);
        if (fits) { ssrc[i] = s; sex[i] = ex; }
        else      { g_e2[start + i] = ex; }
        part += ex;
    }
#pragma unroll
    for (int o = 16; o; o >>= 1) part += __shfl_xor_sync(~0u, part, o);
    if ((tid & 31) == 0) atomicAdd(&sden, part);
    __syncthreads();

    if (tid < OUTC) {
        float acc = 0.f;
        if (fits) {
            int i = 0;
            for (; i + 4 <= deg; i += 4) {
                int s0 = ssrc[i], s1 = ssrc[i + 1], s2 = ssrc[i + 2], s3 = ssrc[i + 3];
                float e0 = sex[i], e1 = sex[i + 1], e2 = sex[i + 2], e3 = sex[i + 3];
                float h0 = g_h2[(size_t)s0 * OUTC + tid];
                float h1 = g_h2[(size_t)s1 * OUTC + tid];
                float h2 = g_h2[(size_t)s2 * OUTC + tid];
                float h3 = g_h2[(size_t)s3 * OUTC + tid];
                acc += e0 * h0 + e1 * h1 + e2 * h2 + e3 * h3;
            }
            for (; i < deg; i++)
                acc += sex[i] * g_h2[(size_t)ssrc[i] * OUTC + tid];
        } else {
            for (int i = 0; i < deg; i++)
                acc += g_e2[start + i] * g_h2[(size_t)g_src[start + i] * OUTC + tid];
        }
        svals[tid] = acc / (sden + 1e-16f) + b2[tid];
    }
    __syncthreads();
    if (tid < OUTC) {
        float m = -1e30f;
#pragma unroll 8
        for (int j = 0; j < OUTC; j++) m = fmaxf(m, svals[j]);
        float sum = 0.f;
#pragma unroll 8
        for (int j = 0; j < OUTC; j++) sum += __expf(svals[j] - m);
        out[(size_t)d * OUTC + tid] = svals[tid] - m - logf(sum);
    }
}

// ---------------- launch --------------------------------------------------------
extern "C" void kernel_launch(void* const* d_in, const int* in_sizes, int n_in,
                              void* d_out, int out_size) {
    const float* x   = (const float*)d_in[0];
    const int*   ei  = (const int*)d_in[1];
    const float* W1  = (const float*)d_in[2];
    const float* a1s = (const float*)d_in[3];
    const float* a1d = (const float*)d_in[4];
    const float* b1  = (const float*)d_in[5];
    const float* W2  = (const float*)d_in[6];
    const float* a2s = (const float*)d_in[7];
    const float* a2d = (const float*)d_in[8];
    const float* b2  = (const float*)d_in[9];
    float*       out = (float*)d_out;

    // CSR build (self-loops folded into degree init)
    init_deg<<<(NN + 255) / 256, 256>>>();
    deg_hist<<<(E0 / 4 + 255) / 256, 256>>>(ei);
    scan_kernel<<<1, 1024>>>();
    fill_csr<<<((ET + 3) / 4 + 255) / 256, 256>>>(ei);

    gemm1_kernel<<<dim3(2, (NN + 127) / 128), 256>>>(x, W1);
    alpha1_kernel<<<NN, 256>>>(a1s, a1d);

    gather1<<<NN, 256>>>(b1);

    gemm2_kernel<<<(NN + 127) / 128, 256>>>(W2, a2s, a2d);

    gather2<<<NN, 64>>>(b2, out);
}

// round 8
// speedup vs baseline: 1.7297x; 1.7297x over previous
#include <cuda_runtime.h>

#define NN   20000
#define INCH 256
#define HEADS 8
#define HID  32
#define C1   256      // HEADS*HID
#define OUTC 40
#define E0   320000
#define ET   340000   // + self loops
#define NEG  0.2f

// ---------------- scratch (device globals; no allocation allowed) ----------
__device__ float g_h1[NN * C1];        // x @ W1
__device__ float g_as1[NN * HEADS];
__device__ float g_ad1[NN * HEADS];
__device__ float g_out1[NN * C1];      // elu(aggr + b1)
__device__ float g_h2[NN * OUTC];      // out1 @ W2
__device__ float g_as2[NN];
__device__ float g_ad2[NN];
__device__ int   g_deg[NN];
__device__ int   g_off[NN + 1];
__device__ int   g_cur[NN];
__device__ int   g_src[ET];            // CSR payload: src node per slot

// ---------------- helpers ---------------------------------------------------
__device__ __forceinline__ unsigned f2tf32(float f) {
    unsigned r;
    asm volatile("cvt.rna.tf32.f32 %0, %1;" : "=r"(r) : "f"(f));
    return r;
}
__device__ __forceinline__ void mma_tf32(float* c, const unsigned* a, unsigned b0, unsigned b1) {
    asm volatile(
        "mma.sync.aligned.m16n8k8.row.col.f32.tf32.tf32.f32 "
        "{%0,%1,%2,%3}, {%4,%5,%6,%7}, {%8,%9}, {%0,%1,%2,%3};"
        : "+f"(c[0]), "+f"(c[1]), "+f"(c[2]), "+f"(c[3])
        : "r"(a[0]), "r"(a[1]), "r"(a[2]), "r"(a[3]), "r"(b0), "r"(b1));
}
__device__ __forceinline__ float lrelu_exp(float v) {
    v = v > 0.f ? v : NEG * v;
    return __expf(v);
}

// ---------------- CSR build --------------------------------------------------
// self-loops folded in: every node starts with degree 1
__global__ void init_deg() {
    int i = blockIdx.x * blockDim.x + threadIdx.x;
    if (i < NN) g_deg[i] = 1;
}

// 1 edge per thread (max thread-level parallelism for latency-bound atomics)
__global__ void deg_hist(const int* __restrict__ ei) {
    int e = blockIdx.x * blockDim.x + threadIdx.x;
    if (e >= E0) return;
    atomicAdd(&g_deg[ei[E0 + e]], 1);
}

// single-block exclusive scan over g_deg -> g_off, g_cur
__global__ __launch_bounds__(1024) void scan_kernel() {
    __shared__ int wsum[32];
    __shared__ int carry_s;
    int tid = threadIdx.x;
    int lane = tid & 31, wid = tid >> 5;
    if (tid == 0) carry_s = 0;
    __syncthreads();
    for (int base = 0; base < NN; base += 1024) {
        int idx = base + tid;
        int v = (idx < NN) ? g_deg[idx] : 0;
        int x = v;
#pragma unroll
        for (int o = 1; o < 32; o <<= 1) {
            int y = __shfl_up_sync(~0u, x, o);
            if (lane >= o) x += y;
        }
        if (lane == 31) wsum[wid] = x;
        __syncthreads();
        if (wid == 0) {
            int w = wsum[lane];
#pragma unroll
            for (int o = 1; o < 32; o <<= 1) {
                int y = __shfl_up_sync(~0u, w, o);
                if (lane >= o) w += y;
            }
            wsum[lane] = w;
        }
        __syncthreads();
        int incl = x + (wid ? wsum[wid - 1] : 0);
        int excl = carry_s + incl - v;
        if (idx < NN) { g_off[idx] = excl; g_cur[idx] = excl; }
        __syncthreads();
        if (tid == 0) carry_s += wsum[31];
        __syncthreads();
    }
    if (tid == 0) g_off[NN] = carry_s;
}

// 1 edge per thread (incl self-loop tail)
__global__ void fill_csr(const int* __restrict__ ei) {
    int e = blockIdx.x * blockDim.x + threadIdx.x;
    if (e >= ET) return;
    int s, d;
    if (e < E0) { s = ei[e]; d = ei[E0 + e]; } else { s = d = e - E0; }
    int pos = atomicAdd(&g_cur[d], 1);
    g_src[pos] = s;
}

// ---------------- GEMM1: h1 = x @ W1  (tf32 tensor cores) -------------------
__global__ __launch_bounds__(256) void gemm1_kernel(const float* __restrict__ x,
                                                    const float* __restrict__ W1) {
    __shared__ float As[128][36];
    __shared__ float Bs[32][136];
    int tid = threadIdx.x;
    int lane = tid & 31, wid = tid >> 5;
    int wm = wid & 3, wn = wid >> 2;
    int g = lane >> 2, tg = lane & 3;
    int m0 = blockIdx.y * 128, n0 = blockIdx.x * 128;

    float acc[2][8][4];
#pragma unroll
    for (int i = 0; i < 2; i++)
#pragma unroll
        for (int j = 0; j < 8; j++)
#pragma unroll
            for (int k = 0; k < 4; k++) acc[i][j][k] = 0.f;

    int a_r = tid >> 3;
    int a_c = (tid & 7) * 4;
    int b_r = tid >> 3;
    int b_c0 = tid & 7;

    for (int k0 = 0; k0 < INCH; k0 += 32) {
#pragma unroll
        for (int j = 0; j < 4; j++) {
            int r = a_r + 32 * j;
            int gm = m0 + r;
            float4 v = make_float4(0.f, 0.f, 0.f, 0.f);
            if (gm < NN) v = *reinterpret_cast<const float4*>(&x[(size_t)gm * INCH + k0 + a_c]);
            As[r][a_c + 0] = __uint_as_float(f2tf32(v.x));
            As[r][a_c + 1] = __uint_as_float(f2tf32(v.y));
            As[r][a_c + 2] = __uint_as_float(f2tf32(v.z));
            As[r][a_c + 3] = __uint_as_float(f2tf32(v.w));
        }
#pragma unroll
        for (int j = 0; j < 4; j++) {
            int c = (b_c0 + 8 * j) * 4;
            float4 v = *reinterpret_cast<const float4*>(&W1[(size_t)(k0 + b_r) * C1 + n0 + c]);
            Bs[b_r][c + 0] = __uint_as_float(f2tf32(v.x));
            Bs[b_r][c + 1] = __uint_as_float(f2tf32(v.y));
            Bs[b_r][c + 2] = __uint_as_float(f2tf32(v.z));
            Bs[b_r][c + 3] = __uint_as_float(f2tf32(v.w));
        }
        __syncthreads();
#pragma unroll
        for (int ks = 0; ks < 4; ks++) {
            int kk = ks * 8;
            unsigned a[2][4];
#pragma unroll
            for (int mi = 0; mi < 2; mi++) {
                int rb = wm * 32 + mi * 16 + g;
                a[mi][0] = __float_as_uint(As[rb][kk + tg]);
                a[mi][1] = __float_as_uint(As[rb + 8][kk + tg]);
                a[mi][2] = __float_as_uint(As[rb][kk + tg + 4]);
                a[mi][3] = __float_as_uint(As[rb + 8][kk + tg + 4]);
            }
#pragma unroll
            for (int nt = 0; nt < 8; nt++) {
                int col = wn * 64 + nt * 8 + g;
                unsigned b0 = __float_as_uint(Bs[kk + tg][col]);
                unsigned b1 = __float_as_uint(Bs[kk + tg + 4][col]);
                mma_tf32(acc[0][nt], a[0], b0, b1);
                mma_tf32(acc[1][nt], a[1], b0, b1);
            }
        }
        __syncthreads();
    }
#pragma unroll
    for (int mi = 0; mi < 2; mi++) {
        int r = m0 + wm * 32 + mi * 16 + g;
#pragma unroll
        for (int nt = 0; nt < 8; nt++) {
            int c = n0 + wn * 64 + nt * 8 + tg * 2;
            if (r < NN) {
                g_h1[(size_t)r * C1 + c]     = acc[mi][nt][0];
                g_h1[(size_t)r * C1 + c + 1] = acc[mi][nt][1];
            }
            if (r + 8 < NN) {
                g_h1[(size_t)(r + 8) * C1 + c]     = acc[mi][nt][2];
                g_h1[(size_t)(r + 8) * C1 + c + 1] = acc[mi][nt][3];
            }
        }
    }
}

// ---------------- alpha projections (layer 1) --------------------------------
__global__ void alpha1_kernel(const float* __restrict__ a_src, const float* __restrict__ a_dst) {
    int n = blockIdx.x;
    int t = threadIdx.x;
    int h = t >> 5, l = t & 31;
    float v = g_h1[n * C1 + t];
    float s = v * a_src[t];
    float d = v * a_dst[t];
#pragma unroll
    for (int o = 16; o; o >>= 1) {
        s += __shfl_xor_sync(~0u, s, o);
        d += __shfl_xor_sync(~0u, d, o);
    }
    if (l == 0) { g_as1[n * HEADS + h] = s; g_ad1[n * HEADS + h] = d; }
}

// ---------------- layer1 gather: warp per node --------------------------------
// lane l owns channels [l*8, l*8+8), head = l>>2.
// per 32-edge wave: lane e preloads src + all-8-head exps (parallel, MLP=32),
// then per edge: shfl src + smem ex + coalesced 1KB h1 row load + 8 FMA/lane.
__global__ __launch_bounds__(256) void gather1(const float* __restrict__ b1) {
    int gw = (blockIdx.x * blockDim.x + threadIdx.x) >> 5;
    int l = threadIdx.x & 31;
    int ws = threadIdx.x >> 5;
    __shared__ float sad[8][8];
    __shared__ float sex[8][32 * 9];   // stride 9 -> conflict-free (gcd(9,32)=1)
    if (gw >= NN) return;
    int d = gw;
    int start = g_off[d];
    int deg = g_off[d + 1] - start;

    if (l < HEADS) sad[ws][l] = g_ad1[d * HEADS + l];
    __syncwarp();

    float acc[8];
#pragma unroll
    for (int j = 0; j < 8; j++) acc[j] = 0.f;
    float den = 0.f;
    int h = l >> 2;

    for (int base = 0; base < deg; base += 32) {
        int cnt = min(32, deg - base);
        int s_l = 0;
        if (l < cnt) {
            s_l = g_src[start + base + l];
            const float4* ap = reinterpret_cast<const float4*>(&g_as1[s_l * HEADS]);
            float4 v0 = ap[0];
            float4 v1 = ap[1];
            float* sx = &sex[ws][l * 9];
            sx[0] = lrelu_exp(v0.x + sad[ws][0]);
            sx[1] = lrelu_exp(v0.y + sad[ws][1]);
            sx[2] = lrelu_exp(v0.z + sad[ws][2]);
            sx[3] = lrelu_exp(v0.w + sad[ws][3]);
            sx[4] = lrelu_exp(v1.x + sad[ws][4]);
            sx[5] = lrelu_exp(v1.y + sad[ws][5]);
            sx[6] = lrelu_exp(v1.z + sad[ws][6]);
            sx[7] = lrelu_exp(v1.w + sad[ws][7]);
        }
        __syncwarp();
#pragma unroll 4
        for (int e = 0; e < cnt; e++) {
            int s = __shfl_sync(~0u, s_l, e);
            float ex = sex[ws][e * 9 + h];
            den += ex;
            const float4* row = reinterpret_cast<const float4*>(&g_h1[(size_t)s * C1 + l * 8]);
            float4 r0 = row[0];
            float4 r1 = row[1];
            acc[0] += ex * r0.x; acc[1] += ex * r0.y;
            acc[2] += ex * r0.z; acc[3] += ex * r0.w;
            acc[4] += ex * r1.x; acc[5] += ex * r1.y;
            acc[6] += ex * r1.z; acc[7] += ex * r1.w;
        }
        __syncwarp();
    }

    float inv = 1.f / (den + 1e-16f);
    int chb = l * 8;
    float o[8];
#pragma unroll
    for (int j = 0; j < 8; j++) {
        float v = acc[j] * inv + b1[chb + j];
        o[j] = v > 0.f ? v : expm1f(v);
    }
    float4* dst = reinterpret_cast<float4*>(&g_out1[(size_t)d * C1 + chb]);
    dst[0] = make_float4(o[0], o[1], o[2], o[3]);
    dst[1] = make_float4(o[4], o[5], o[6], o[7]);
}

// ---------------- GEMM2: h2 = out1 @ W2, + fused alpha2 ---------------------
__global__ __launch_bounds__(256) void gemm2_kernel(const float* __restrict__ W2,
                                                    const float* __restrict__ a2s,
                                                    const float* __restrict__ a2d) {
    __shared__ float As[128][36];
    __shared__ float Bs[32][44];
    int tid = threadIdx.x;
    int lane = tid & 31, wid = tid >> 5;
    int g = lane >> 2, tg = lane & 3;
    int m0 = blockIdx.x * 128;

    float acc[5][4];
#pragma unroll
    for (int j = 0; j < 5; j++)
#pragma unroll
        for (int k = 0; k < 4; k++) acc[j][k] = 0.f;

    int a_r = tid >> 3;
    int a_c = (tid & 7) * 4;

    for (int k0 = 0; k0 < C1; k0 += 32) {
#pragma unroll
        for (int j = 0; j < 4; j++) {
            int r = a_r + 32 * j;
            int gm = m0 + r;
            float4 v = make_float4(0.f, 0.f, 0.f, 0.f);
            if (gm < NN) v = *reinterpret_cast<const float4*>(&g_out1[(size_t)gm * C1 + k0 + a_c]);
            As[r][a_c + 0] = __uint_as_float(f2tf32(v.x));
            As[r][a_c + 1] = __uint_as_float(f2tf32(v.y));
            As[r][a_c + 2] = __uint_as_float(f2tf32(v.z));
            As[r][a_c + 3] = __uint_as_float(f2tf32(v.w));
        }
        for (int idx = tid; idx < 32 * OUTC; idx += 256) {
            int r = idx / OUTC, c = idx % OUTC;
            Bs[r][c] = __uint_as_float(f2tf32(W2[(size_t)(k0 + r) * OUTC + c]));
        }
        __syncthreads();
#pragma unroll
        for (int ks = 0; ks < 4; ks++) {
            int kk = ks * 8;
            unsigned a[4];
            int rb = wid * 16 + g;
            a[0] = __float_as_uint(As[rb][kk + tg]);
            a[1] = __float_as_uint(As[rb + 8][kk + tg]);
            a[2] = __float_as_uint(As[rb][kk + tg + 4]);
            a[3] = __float_as_uint(As[rb + 8][kk + tg + 4]);
#pragma unroll
            for (int nt = 0; nt < 5; nt++) {
                int col = nt * 8 + g;
                unsigned b0 = __float_as_uint(Bs[kk + tg][col]);
                unsigned b1r = __float_as_uint(Bs[kk + tg + 4][col]);
                mma_tf32(acc[nt], a, b0, b1r);
            }
        }
        __syncthreads();
    }
    int rlo = m0 + wid * 16 + g;
    int rhi = rlo + 8;
    float s_lo = 0.f, s_hi = 0.f, d_lo = 0.f, d_hi = 0.f;
#pragma unroll
    for (int nt = 0; nt < 5; nt++) {
        int c = nt * 8 + tg * 2;
        float w0s = a2s[c], w1s = a2s[c + 1];
        float w0d = a2d[c], w1d = a2d[c + 1];
        if (rlo < NN) {
            g_h2[(size_t)rlo * OUTC + c]     = acc[nt][0];
            g_h2[(size_t)rlo * OUTC + c + 1] = acc[nt][1];
        }
        if (rhi < NN) {
            g_h2[(size_t)rhi * OUTC + c]     = acc[nt][2];
            g_h2[(size_t)rhi * OUTC + c + 1] = acc[nt][3];
        }
        s_lo += acc[nt][0] * w0s + acc[nt][1] * w1s;
        s_hi += acc[nt][2] * w0s + acc[nt][3] * w1s;
        d_lo += acc[nt][0] * w0d + acc[nt][1] * w1d;
        d_hi += acc[nt][2] * w0d + acc[nt][3] * w1d;
    }
#pragma unroll
    for (int o = 1; o <= 2; o <<= 1) {
        s_lo += __shfl_xor_sync(~0u, s_lo, o);
        s_hi += __shfl_xor_sync(~0u, s_hi, o);
        d_lo += __shfl_xor_sync(~0u, d_lo, o);
        d_hi += __shfl_xor_sync(~0u, d_hi, o);
    }
    if (tg == 0) {
        if (rlo < NN) { g_as2[rlo] = s_lo; g_ad2[rlo] = d_lo; }
        if (rhi < NN) { g_as2[rhi] = s_hi; g_ad2[rhi] = d_hi; }
    }
}

// ---------------- layer2 gather: warp per node, fused log_softmax ------------
__global__ __launch_bounds__(256) void gather2(const float* __restrict__ b2,
                                               float* __restrict__ out) {
    int gw = (blockIdx.x * blockDim.x + threadIdx.x) >> 5;
    int l = threadIdx.x & 31;
    if (gw >= NN) return;
    int d = gw;
    int start = g_off[d];
    int deg = g_off[d + 1] - start;

    float ad = g_ad2[d];
    float acc0 = 0.f, acc1 = 0.f, denp = 0.f;

    for (int base = 0; base < deg; base += 32) {
        int cnt = min(32, deg - base);
        int s_l = 0;
        float ex_l = 0.f;
        if (l < cnt) {
            s_l = g_src[start + base + l];
            ex_l = lrelu_exp(g_as2[s_l] + ad);
        }
        denp += ex_l;
#pragma unroll 4
        for (int e = 0; e < cnt; e++) {
            int s = __shfl_sync(~0u, s_l, e);
            float ex = __shfl_sync(~0u, ex_l, e);
            acc0 += ex * g_h2[(size_t)s * OUTC + l];
            if (l < 8) acc1 += ex * g_h2[(size_t)s * OUTC + 32 + l];
        }
    }
    float den = denp;
#pragma unroll
    for (int o = 16; o; o >>= 1) den += __shfl_xor_sync(~0u, den, o);
    float inv = 1.f / (den + 1e-16f);

    float v1 = acc0 * inv + b2[l];
    float v2 = (l < 8) ? (acc1 * inv + b2[32 + l]) : -1e30f;
    float m = fmaxf(v1, v2);
#pragma unroll
    for (int o = 16; o; o >>= 1) m = fmaxf(m, __shfl_xor_sync(~0u, m, o));
    float sum = __expf(v1 - m) + ((l < 8) ? __expf(v2 - m) : 0.f);
#pragma unroll
    for (int o = 16; o; o >>= 1) sum += __shfl_xor_sync(~0u, sum, o);
    float lse = m + logf(sum);
    out[(size_t)d * OUTC + l] = v1 - lse;
    if (l < 8) out[(size_t)d * OUTC + 32 + l] = v2 - lse;
}

// ---------------- launch --------------------------------------------------------
extern "C" void kernel_launch(void* const* d_in, const int* in_sizes, int n_in,
                              void* d_out, int out_size) {
    const float* x   = (const float*)d_in[0];
    const int*   ei  = (const int*)d_in[1];
    const float* W1  = (const float*)d_in[2];
    const float* a1s = (const float*)d_in[3];
    const float* a1d = (const float*)d_in[4];
    const float* b1  = (const float*)d_in[5];
    const float* W2  = (const float*)d_in[6];
    const float* a2s = (const float*)d_in[7];
    const float* a2d = (const float*)d_in[8];
    const float* b2  = (const float*)d_in[9];
    float*       out = (float*)d_out;

    // CSR build (self-loops folded into degree init)
    init_deg<<<(NN + 255) / 256, 256>>>();
    deg_hist<<<(E0 + 255) / 256, 256>>>(ei);
    scan_kernel<<<1, 1024>>>();
    fill_csr<<<(ET + 255) / 256, 256>>>(ei);

    gemm1_kernel<<<dim3(2, (NN + 127) / 128), 256>>>(x, W1);
    alpha1_kernel<<<NN, 256>>>(a1s, a1d);

    gather1<<<(NN * 32 + 255) / 256, 256>>>(b1);

    gemm2_kernel<<<(NN + 127) / 128, 256>>>(W2, a2s, a2d);

    gather2<<<(NN * 32 + 255) / 256, 256>>>(b2, out);
}

// round 9
// speedup vs baseline: 1.8806x; 1.0873x over previous
#include <cuda_runtime.h>

#define NN   20000
#define INCH 256
#define HEADS 8
#define HID  32
#define C1   256      // HEADS*HID
#define OUTC 40
#define E0   320000
#define ET   340000   // + self loops
#define NEG  0.2f

// ---------------- scratch (device globals; no allocation allowed) ----------
__device__ float g_h1[NN * C1];        // x @ W1
__device__ float g_as1[NN * HEADS];
__device__ float g_ad1[NN * HEADS];
__device__ float g_out1[NN * C1];      // elu(aggr + b1)
__device__ float g_h2[NN * OUTC];      // out1 @ W2
__device__ float g_as2[NN];
__device__ float g_ad2[NN];
__device__ int   g_deg[NN];
__device__ int   g_off[NN + 1];
__device__ int   g_cur[NN];
__device__ int   g_src[ET];            // CSR payload: src node per slot

// ---------------- helpers ---------------------------------------------------
__device__ __forceinline__ unsigned f2tf32(float f) {
    unsigned r;
    asm volatile("cvt.rna.tf32.f32 %0, %1;" : "=r"(r) : "f"(f));
    return r;
}
__device__ __forceinline__ void mma_tf32(float* c, const unsigned* a, unsigned b0, unsigned b1) {
    asm volatile(
        "mma.sync.aligned.m16n8k8.row.col.f32.tf32.tf32.f32 "
        "{%0,%1,%2,%3}, {%4,%5,%6,%7}, {%8,%9}, {%0,%1,%2,%3};"
        : "+f"(c[0]), "+f"(c[1]), "+f"(c[2]), "+f"(c[3])
        : "r"(a[0]), "r"(a[1]), "r"(a[2]), "r"(a[3]), "r"(b0), "r"(b1));
}
__device__ __forceinline__ float lrelu_exp(float v) {
    v = v > 0.f ? v : NEG * v;
    return __expf(v);
}

// ---------------- CSR build --------------------------------------------------
// self-loops folded in: every node starts with degree 1
__global__ void init_deg() {
    int i = blockIdx.x * blockDim.x + threadIdx.x;
    if (i < NN) g_deg[i] = 1;
}

// 1 edge per thread (max thread-level parallelism for latency-bound atomics)
__global__ void deg_hist(const int* __restrict__ ei) {
    int e = blockIdx.x * blockDim.x + threadIdx.x;
    if (e >= E0) return;
    atomicAdd(&g_deg[ei[E0 + e]], 1);
}

// single-block exclusive scan over g_deg -> g_off, g_cur
// also pre-places the self-loop at each node's first CSR slot
__global__ __launch_bounds__(1024) void scan_kernel() {
    __shared__ int wsum[32];
    __shared__ int carry_s;
    int tid = threadIdx.x;
    int lane = tid & 31, wid = tid >> 5;
    if (tid == 0) carry_s = 0;
    __syncthreads();
    for (int base = 0; base < NN; base += 1024) {
        int idx = base + tid;
        int v = (idx < NN) ? g_deg[idx] : 0;
        int x = v;
#pragma unroll
        for (int o = 1; o < 32; o <<= 1) {
            int y = __shfl_up_sync(~0u, x, o);
            if (lane >= o) x += y;
        }
        if (lane == 31) wsum[wid] = x;
        __syncthreads();
        if (wid == 0) {
            int w = wsum[lane];
#pragma unroll
            for (int o = 1; o < 32; o <<= 1) {
                int y = __shfl_up_sync(~0u, w, o);
                if (lane >= o) w += y;
            }
            wsum[lane] = w;
        }
        __syncthreads();
        int incl = x + (wid ? wsum[wid - 1] : 0);
        int excl = carry_s + incl - v;
        if (idx < NN) {
            g_off[idx] = excl;
            g_cur[idx] = excl + 1;   // slot 0 taken by self-loop
            g_src[excl] = idx;       // self-loop
        }
        __syncthreads();
        if (tid == 0) carry_s += wsum[31];
        __syncthreads();
    }
    if (tid == 0) g_off[NN] = carry_s;
}

// 1 edge per thread, E0 edges only (self-loops already placed)
__global__ void fill_csr(const int* __restrict__ ei) {
    int e = blockIdx.x * blockDim.x + threadIdx.x;
    if (e >= E0) return;
    int s = ei[e];
    int d = ei[E0 + e];
    int pos = atomicAdd(&g_cur[d], 1);
    g_src[pos] = s;
}

// ---------------- GEMM1: h1 = x @ W1 (tf32, pipelined) + fused alpha1 -------
__global__ __launch_bounds__(256) void gemm1_kernel(const float* __restrict__ x,
                                                    const float* __restrict__ W1,
                                                    const float* __restrict__ a1s,
                                                    const float* __restrict__ a1d) {
    __shared__ float As[128][36];
    __shared__ float Bs[32][136];
    int tid = threadIdx.x;
    int lane = tid & 31, wid = tid >> 5;
    int wm = wid & 3, wn = wid >> 2;
    int g = lane >> 2, tg = lane & 3;
    int m0 = blockIdx.y * 128, n0 = blockIdx.x * 128;

    float acc[2][8][4];
#pragma unroll
    for (int i = 0; i < 2; i++)
#pragma unroll
        for (int j = 0; j < 8; j++)
#pragma unroll
            for (int k = 0; k < 4; k++) acc[i][j][k] = 0.f;

    int a_r = tid >> 3;
    int a_c = (tid & 7) * 4;
    int b_r = tid >> 3;
    int b_c0 = tid & 7;

    float4 pa[4], pb[4];
    // prologue load k0 = 0
#pragma unroll
    for (int j = 0; j < 4; j++) {
        int gm = m0 + a_r + 32 * j;
        pa[j] = make_float4(0.f, 0.f, 0.f, 0.f);
        if (gm < NN) pa[j] = *reinterpret_cast<const float4*>(&x[(size_t)gm * INCH + a_c]);
        pb[j] = *reinterpret_cast<const float4*>(&W1[(size_t)b_r * C1 + n0 + (b_c0 + 8 * j) * 4]);
    }

    for (int k0 = 0; k0 < INCH; k0 += 32) {
        // commit prefetched tiles to smem
#pragma unroll
        for (int j = 0; j < 4; j++) {
            int r = a_r + 32 * j;
            As[r][a_c + 0] = __uint_as_float(f2tf32(pa[j].x));
            As[r][a_c + 1] = __uint_as_float(f2tf32(pa[j].y));
            As[r][a_c + 2] = __uint_as_float(f2tf32(pa[j].z));
            As[r][a_c + 3] = __uint_as_float(f2tf32(pa[j].w));
            int c = (b_c0 + 8 * j) * 4;
            Bs[b_r][c + 0] = __uint_as_float(f2tf32(pb[j].x));
            Bs[b_r][c + 1] = __uint_as_float(f2tf32(pb[j].y));
            Bs[b_r][c + 2] = __uint_as_float(f2tf32(pb[j].z));
            Bs[b_r][c + 3] = __uint_as_float(f2tf32(pb[j].w));
        }
        __syncthreads();
        // prefetch next K tile (overlaps with MMAs below)
        int kn = k0 + 32;
        if (kn < INCH) {
#pragma unroll
            for (int j = 0; j < 4; j++) {
                int gm = m0 + a_r + 32 * j;
                pa[j] = make_float4(0.f, 0.f, 0.f, 0.f);
                if (gm < NN) pa[j] = *reinterpret_cast<const float4*>(&x[(size_t)gm * INCH + kn + a_c]);
                pb[j] = *reinterpret_cast<const float4*>(&W1[(size_t)(kn + b_r) * C1 + n0 + (b_c0 + 8 * j) * 4]);
            }
        }
#pragma unroll
        for (int ks = 0; ks < 4; ks++) {
            int kk = ks * 8;
            unsigned a[2][4];
#pragma unroll
            for (int mi = 0; mi < 2; mi++) {
                int rb = wm * 32 + mi * 16 + g;
                a[mi][0] = __float_as_uint(As[rb][kk + tg]);
                a[mi][1] = __float_as_uint(As[rb + 8][kk + tg]);
                a[mi][2] = __float_as_uint(As[rb][kk + tg + 4]);
                a[mi][3] = __float_as_uint(As[rb + 8][kk + tg + 4]);
            }
#pragma unroll
            for (int nt = 0; nt < 8; nt++) {
                int col = wn * 64 + nt * 8 + g;
                unsigned b0 = __float_as_uint(Bs[kk + tg][col]);
                unsigned b1 = __float_as_uint(Bs[kk + tg + 4][col]);
                mma_tf32(acc[0][nt], a[0], b0, b1);
                mma_tf32(acc[1][nt], a[1], b0, b1);
            }
        }
        __syncthreads();
    }

    // epilogue: store h1 + fused alpha1 partials
    // per thread: partial dots for rows {r, r+8} x head_local {0,1}
    float ps[2][2][2] = {}, pd[2][2][2] = {};
#pragma unroll
    for (int mi = 0; mi < 2; mi++) {
        int r = m0 + wm * 32 + mi * 16 + g;
#pragma unroll
        for (int nt = 0; nt < 8; nt++) {
            int c = n0 + wn * 64 + nt * 8 + tg * 2;
            int hl = nt >> 2;
            float w0s = a1s[c], w1s = a1s[c + 1];
            float w0d = a1d[c], w1d = a1d[c + 1];
            if (r < NN) {
                g_h1[(size_t)r * C1 + c]     = acc[mi][nt][0];
                g_h1[(size_t)r * C1 + c + 1] = acc[mi][nt][1];
            }
            if (r + 8 < NN) {
                g_h1[(size_t)(r + 8) * C1 + c]     = acc[mi][nt][2];
                g_h1[(size_t)(r + 8) * C1 + c + 1] = acc[mi][nt][3];
            }
            ps[mi][0][hl] += acc[mi][nt][0] * w0s + acc[mi][nt][1] * w1s;
            ps[mi][1][hl] += acc[mi][nt][2] * w0s + acc[mi][nt][3] * w1s;
            pd[mi][0][hl] += acc[mi][nt][0] * w0d + acc[mi][nt][1] * w1d;
            pd[mi][1][hl] += acc[mi][nt][2] * w0d + acc[mi][nt][3] * w1d;
        }
    }
    // quad reduce over tg (lane bits 0-1)
#pragma unroll
    for (int mi = 0; mi < 2; mi++)
#pragma unroll
        for (int rh = 0; rh < 2; rh++)
#pragma unroll
            for (int hl = 0; hl < 2; hl++) {
                float s = ps[mi][rh][hl], d = pd[mi][rh][hl];
                s += __shfl_xor_sync(~0u, s, 1); s += __shfl_xor_sync(~0u, s, 2);
                d += __shfl_xor_sync(~0u, d, 1); d += __shfl_xor_sync(~0u, d, 2);
                if (tg == 0) {
                    int r = m0 + wm * 32 + mi * 16 + g + rh * 8;
                    if (r < NN) {
                        int head = (n0 >> 5) + wn * 2 + hl;
                        g_as1[r * HEADS + head] = s;
                        g_ad1[r * HEADS + head] = d;
                    }
                }
            }
}

// ---------------- layer1 gather: warp per node --------------------------------
__global__ __launch_bounds__(256) void gather1(const float* __restrict__ b1) {
    int gw = (blockIdx.x * blockDim.x + threadIdx.x) >> 5;
    int l = threadIdx.x & 31;
    int ws = threadIdx.x >> 5;
    __shared__ float sad[8][8];
    __shared__ float sex[8][32 * 9];   // stride 9 -> conflict-free
    if (gw >= NN) return;
    int d = gw;
    int start = g_off[d];
    int deg = g_off[d + 1] - start;

    if (l < HEADS) sad[ws][l] = g_ad1[d * HEADS + l];
    __syncwarp();

    float acc[8];
#pragma unroll
    for (int j = 0; j < 8; j++) acc[j] = 0.f;
    float den = 0.f;
    int h = l >> 2;

    for (int base = 0; base < deg; base += 32) {
        int cnt = min(32, deg - base);
        int s_l = 0;
        if (l < cnt) {
            s_l = g_src[start + base + l];
            const float4* ap = reinterpret_cast<const float4*>(&g_as1[s_l * HEADS]);
            float4 v0 = ap[0];
            float4 v1 = ap[1];
            float* sx = &sex[ws][l * 9];
            sx[0] = lrelu_exp(v0.x + sad[ws][0]);
            sx[1] = lrelu_exp(v0.y + sad[ws][1]);
            sx[2] = lrelu_exp(v0.z + sad[ws][2]);
            sx[3] = lrelu_exp(v0.w + sad[ws][3]);
            sx[4] = lrelu_exp(v1.x + sad[ws][4]);
            sx[5] = lrelu_exp(v1.y + sad[ws][5]);
            sx[6] = lrelu_exp(v1.z + sad[ws][6]);
            sx[7] = lrelu_exp(v1.w + sad[ws][7]);
        }
        __syncwarp();
#pragma unroll 4
        for (int e = 0; e < cnt; e++) {
            int s = __shfl_sync(~0u, s_l, e);
            float ex = sex[ws][e * 9 + h];
            den += ex;
            const float4* row = reinterpret_cast<const float4*>(&g_h1[(size_t)s * C1 + l * 8]);
            float4 r0 = row[0];
            float4 r1 = row[1];
            acc[0] += ex * r0.x; acc[1] += ex * r0.y;
            acc[2] += ex * r0.z; acc[3] += ex * r0.w;
            acc[4] += ex * r1.x; acc[5] += ex * r1.y;
            acc[6] += ex * r1.z; acc[7] += ex * r1.w;
        }
        __syncwarp();
    }

    float inv = 1.f / (den + 1e-16f);
    int chb = l * 8;
    float o[8];
#pragma unroll
    for (int j = 0; j < 8; j++) {
        float v = acc[j] * inv + b1[chb + j];
        o[j] = v > 0.f ? v : expm1f(v);
    }
    float4* dst = reinterpret_cast<float4*>(&g_out1[(size_t)d * C1 + chb]);
    dst[0] = make_float4(o[0], o[1], o[2], o[3]);
    dst[1] = make_float4(o[4], o[5], o[6], o[7]);
}

// ---------------- GEMM2: h2 = out1 @ W2, + fused alpha2 ---------------------
__global__ __launch_bounds__(256) void gemm2_kernel(const float* __restrict__ W2,
                                                    const float* __restrict__ a2s,
                                                    const float* __restrict__ a2d) {
    __shared__ float As[128][36];
    __shared__ float Bs[32][44];
    int tid = threadIdx.x;
    int lane = tid & 31, wid = tid >> 5;
    int g = lane >> 2, tg = lane & 3;
    int m0 = blockIdx.x * 128;

    float acc[5][4];
#pragma unroll
    for (int j = 0; j < 5; j++)
#pragma unroll
        for (int k = 0; k < 4; k++) acc[j][k] = 0.f;

    int a_r = tid >> 3;
    int a_c = (tid & 7) * 4;

    for (int k0 = 0; k0 < C1; k0 += 32) {
#pragma unroll
        for (int j = 0; j < 4; j++) {
            int r = a_r + 32 * j;
            int gm = m0 + r;
            float4 v = make_float4(0.f, 0.f, 0.f, 0.f);
            if (gm < NN) v = *reinterpret_cast<const float4*>(&g_out1[(size_t)gm * C1 + k0 + a_c]);
            As[r][a_c + 0] = __uint_as_float(f2tf32(v.x));
            As[r][a_c + 1] = __uint_as_float(f2tf32(v.y));
            As[r][a_c + 2] = __uint_as_float(f2tf32(v.z));
            As[r][a_c + 3] = __uint_as_float(f2tf32(v.w));
        }
        for (int idx = tid; idx < 32 * OUTC; idx += 256) {
            int r = idx / OUTC, c = idx % OUTC;
            Bs[r][c] = __uint_as_float(f2tf32(W2[(size_t)(k0 + r) * OUTC + c]));
        }
        __syncthreads();
#pragma unroll
        for (int ks = 0; ks < 4; ks++) {
            int kk = ks * 8;
            unsigned a[4];
            int rb = wid * 16 + g;
            a[0] = __float_as_uint(As[rb][kk + tg]);
            a[1] = __float_as_uint(As[rb + 8][kk + tg]);
            a[2] = __float_as_uint(As[rb][kk + tg + 4]);
            a[3] = __float_as_uint(As[rb + 8][kk + tg + 4]);
#pragma unroll
            for (int nt = 0; nt < 5; nt++) {
                int col = nt * 8 + g;
                unsigned b0 = __float_as_uint(Bs[kk + tg][col]);
                unsigned b1r = __float_as_uint(Bs[kk + tg + 4][col]);
                mma_tf32(acc[nt], a, b0, b1r);
            }
        }
        __syncthreads();
    }
    int rlo = m0 + wid * 16 + g;
    int rhi = rlo + 8;
    float s_lo = 0.f, s_hi = 0.f, d_lo = 0.f, d_hi = 0.f;
#pragma unroll
    for (int nt = 0; nt < 5; nt++) {
        int c = nt * 8 + tg * 2;
        float w0s = a2s[c], w1s = a2s[c + 1];
        float w0d = a2d[c], w1d = a2d[c + 1];
        if (rlo < NN) {
            g_h2[(size_t)rlo * OUTC + c]     = acc[nt][0];
            g_h2[(size_t)rlo * OUTC + c + 1] = acc[nt][1];
        }
        if (rhi < NN) {
            g_h2[(size_t)rhi * OUTC + c]     = acc[nt][2];
            g_h2[(size_t)rhi * OUTC + c + 1] = acc[nt][3];
        }
        s_lo += acc[nt][0] * w0s + acc[nt][1] * w1s;
        s_hi += acc[nt][2] * w0s + acc[nt][3] * w1s;
        d_lo += acc[nt][0] * w0d + acc[nt][1] * w1d;
        d_hi += acc[nt][2] * w0d + acc[nt][3] * w1d;
    }
#pragma unroll
    for (int o = 1; o <= 2; o <<= 1) {
        s_lo += __shfl_xor_sync(~0u, s_lo, o);
        s_hi += __shfl_xor_sync(~0u, s_hi, o);
        d_lo += __shfl_xor_sync(~0u, d_lo, o);
        d_hi += __shfl_xor_sync(~0u, d_hi, o);
    }
    if (tg == 0) {
        if (rlo < NN) { g_as2[rlo] = s_lo; g_ad2[rlo] = d_lo; }
        if (rhi < NN) { g_as2[rhi] = s_hi; g_ad2[rhi] = d_hi; }
    }
}

// ---------------- layer2 gather: warp per node, fused log_softmax ------------
__global__ __launch_bounds__(256) void gather2(const float* __restrict__ b2,
                                               float* __restrict__ out) {
    int gw = (blockIdx.x * blockDim.x + threadIdx.x) >> 5;
    int l = threadIdx.x & 31;
    if (gw >= NN) return;
    int d = gw;
    int start = g_off[d];
    int deg = g_off[d + 1] - start;

    float ad = g_ad2[d];
    float acc0 = 0.f, acc1 = 0.f, denp = 0.f;

    for (int base = 0; base < deg; base += 32) {
        int cnt = min(32, deg - base);
        int s_l = 0;
        float ex_l = 0.f;
        if (l < cnt) {
            s_l = g_src[start + base + l];
            ex_l = lrelu_exp(g_as2[s_l] + ad);
        }
        denp += ex_l;
#pragma unroll 4
        for (int e = 0; e < cnt; e++) {
            int s = __shfl_sync(~0u, s_l, e);
            float ex = __shfl_sync(~0u, ex_l, e);
            acc0 += ex * g_h2[(size_t)s * OUTC + l];
            if (l < 8) acc1 += ex * g_h2[(size_t)s * OUTC + 32 + l];
        }
    }
    float den = denp;
#pragma unroll
    for (int o = 16; o; o >>= 1) den += __shfl_xor_sync(~0u, den, o);
    float inv = 1.f / (den + 1e-16f);

    float v1 = acc0 * inv + b2[l];
    float v2 = (l < 8) ? (acc1 * inv + b2[32 + l]) : -1e30f;
    float m = fmaxf(v1, v2);
#pragma unroll
    for (int o = 16; o; o >>= 1) m = fmaxf(m, __shfl_xor_sync(~0u, m, o));
    float sum = __expf(v1 - m) + ((l < 8) ? __expf(v2 - m) : 0.f);
#pragma unroll
    for (int o = 16; o; o >>= 1) sum += __shfl_xor_sync(~0u, sum, o);
    float lse = m + logf(sum);
    out[(size_t)d * OUTC + l] = v1 - lse;
    if (l < 8) out[(size_t)d * OUTC + 32 + l] = v2 - lse;
}

// ---------------- launch --------------------------------------------------------
extern "C" void kernel_launch(void* const* d_in, const int* in_sizes, int n_in,
                              void* d_out, int out_size) {
    const float* x   = (const float*)d_in[0];
    const int*   ei  = (const int*)d_in[1];
    const float* W1  = (const float*)d_in[2];
    const float* a1s = (const float*)d_in[3];
    const float* a1d = (const float*)d_in[4];
    const float* b1  = (const float*)d_in[5];
    const float* W2  = (const float*)d_in[6];
    const float* a2s = (const float*)d_in[7];
    const float* a2d = (const float*)d_in[8];
    const float* b2  = (const float*)d_in[9];
    float*       out = (float*)d_out;

    // CSR build (self-loops pre-placed in scan)
    init_deg<<<(NN + 255) / 256, 256>>>();
    deg_hist<<<(E0 + 255) / 256, 256>>>(ei);
    scan_kernel<<<1, 1024>>>();
    fill_csr<<<(E0 + 255) / 256, 256>>>(ei);

    gemm1_kernel<<<dim3(2, (NN + 127) / 128), 256>>>(x, W1, a1s, a1d);

    gather1<<<(NN * 32 + 255) / 256, 256>>>(b1);

    gemm2_kernel<<<(NN + 127) / 128, 256>>>(W2, a2s, a2d);

    gather2<<<(NN * 32 + 255) / 256, 256>>>(b2, out);
}

// round 10
// speedup vs baseline: 2.1212x; 1.1279x over previous
#include <cuda_runtime.h>
#include <cuda_bf16.h>

#define NN   20000
#define INCH 256
#define HEADS 8
#define HID  32
#define C1   256      // HEADS*HID
#define OUTC 40
#define E0   320000
#define ET   340000   // + self loops
#define NEG  0.2f

// ---------------- scratch (device globals; no allocation allowed) ----------
__device__ __nv_bfloat16 g_h1[NN * C1];   // x @ W1 (bf16: halves gather1 traffic)
__device__ float g_as1[NN * HEADS];
__device__ float g_ad1[NN * HEADS];
__device__ float g_out1[NN * C1];         // elu(aggr + b1)
__device__ float g_h2[NN * OUTC];         // out1 @ W2
__device__ float g_as2[NN];
__device__ float g_ad2[NN];
__device__ int   g_deg[NN];
__device__ int   g_off[NN + 1];
__device__ int   g_cur[NN];
__device__ int   g_src[ET];               // CSR payload: src node per slot

// ---------------- helpers ---------------------------------------------------
__device__ __forceinline__ unsigned f2tf32(float f) {
    unsigned r;
    asm volatile("cvt.rna.tf32.f32 %0, %1;" : "=r"(r) : "f"(f));
    return r;
}
__device__ __forceinline__ void mma_tf32(float* c, const unsigned* a, unsigned b0, unsigned b1) {
    asm volatile(
        "mma.sync.aligned.m16n8k8.row.col.f32.tf32.tf32.f32 "
        "{%0,%1,%2,%3}, {%4,%5,%6,%7}, {%8,%9}, {%0,%1,%2,%3};"
        : "+f"(c[0]), "+f"(c[1]), "+f"(c[2]), "+f"(c[3])
        : "r"(a[0]), "r"(a[1]), "r"(a[2]), "r"(a[3]), "r"(b0), "r"(b1));
}
__device__ __forceinline__ float lrelu_exp(float v) {
    v = v > 0.f ? v : NEG * v;
    return __expf(v);
}

// ---------------- CSR build --------------------------------------------------
__global__ void init_deg() {
    int i = blockIdx.x * blockDim.x + threadIdx.x;
    if (i < NN) g_deg[i] = 1;   // self-loop folded in
}

__global__ void deg_hist(const int* __restrict__ ei) {
    int e = blockIdx.x * blockDim.x + threadIdx.x;
    if (e >= E0) return;
    atomicAdd(&g_deg[ei[E0 + e]], 1);
}

// single-block exclusive scan; pre-places self-loop at each node's slot 0
__global__ __launch_bounds__(1024) void scan_kernel() {
    __shared__ int wsum[32];
    __shared__ int carry_s;
    int tid = threadIdx.x;
    int lane = tid & 31, wid = tid >> 5;
    if (tid == 0) carry_s = 0;
    __syncthreads();
    for (int base = 0; base < NN; base += 1024) {
        int idx = base + tid;
        int v = (idx < NN) ? g_deg[idx] : 0;
        int x = v;
#pragma unroll
        for (int o = 1; o < 32; o <<= 1) {
            int y = __shfl_up_sync(~0u, x, o);
            if (lane >= o) x += y;
        }
        if (lane == 31) wsum[wid] = x;
        __syncthreads();
        if (wid == 0) {
            int w = wsum[lane];
#pragma unroll
            for (int o = 1; o < 32; o <<= 1) {
                int y = __shfl_up_sync(~0u, w, o);
                if (lane >= o) w += y;
            }
            wsum[lane] = w;
        }
        __syncthreads();
        int incl = x + (wid ? wsum[wid - 1] : 0);
        int excl = carry_s + incl - v;
        if (idx < NN) {
            g_off[idx] = excl;
            g_cur[idx] = excl + 1;   // slot 0 taken by self-loop
            g_src[excl] = idx;       // self-loop
        }
        __syncthreads();
        if (tid == 0) carry_s += wsum[31];
        __syncthreads();
    }
    if (tid == 0) g_off[NN] = carry_s;
}

__global__ void fill_csr(const int* __restrict__ ei) {
    int e = blockIdx.x * blockDim.x + threadIdx.x;
    if (e >= E0) return;
    int s = ei[e];
    int d = ei[E0 + e];
    int pos = atomicAdd(&g_cur[d], 1);
    g_src[pos] = s;
}

// ---------------- GEMM1: h1 = x @ W1 (tf32, pipelined) + fused alpha1 -------
__global__ __launch_bounds__(256) void gemm1_kernel(const float* __restrict__ x,
                                                    const float* __restrict__ W1,
                                                    const float* __restrict__ a1s,
                                                    const float* __restrict__ a1d) {
    __shared__ float As[128][36];
    __shared__ float Bs[32][136];
    int tid = threadIdx.x;
    int lane = tid & 31, wid = tid >> 5;
    int wm = wid & 3, wn = wid >> 2;
    int g = lane >> 2, tg = lane & 3;
    int m0 = blockIdx.y * 128, n0 = blockIdx.x * 128;

    float acc[2][8][4];
#pragma unroll
    for (int i = 0; i < 2; i++)
#pragma unroll
        for (int j = 0; j < 8; j++)
#pragma unroll
            for (int k = 0; k < 4; k++) acc[i][j][k] = 0.f;

    int a_r = tid >> 3;
    int a_c = (tid & 7) * 4;
    int b_r = tid >> 3;
    int b_c0 = tid & 7;

    float4 pa[4], pb[4];
#pragma unroll
    for (int j = 0; j < 4; j++) {
        int gm = m0 + a_r + 32 * j;
        pa[j] = make_float4(0.f, 0.f, 0.f, 0.f);
        if (gm < NN) pa[j] = *reinterpret_cast<const float4*>(&x[(size_t)gm * INCH + a_c]);
        pb[j] = *reinterpret_cast<const float4*>(&W1[(size_t)b_r * C1 + n0 + (b_c0 + 8 * j) * 4]);
    }

    for (int k0 = 0; k0 < INCH; k0 += 32) {
#pragma unroll
        for (int j = 0; j < 4; j++) {
            int r = a_r + 32 * j;
            As[r][a_c + 0] = __uint_as_float(f2tf32(pa[j].x));
            As[r][a_c + 1] = __uint_as_float(f2tf32(pa[j].y));
            As[r][a_c + 2] = __uint_as_float(f2tf32(pa[j].z));
            As[r][a_c + 3] = __uint_as_float(f2tf32(pa[j].w));
            int c = (b_c0 + 8 * j) * 4;
            Bs[b_r][c + 0] = __uint_as_float(f2tf32(pb[j].x));
            Bs[b_r][c + 1] = __uint_as_float(f2tf32(pb[j].y));
            Bs[b_r][c + 2] = __uint_as_float(f2tf32(pb[j].z));
            Bs[b_r][c + 3] = __uint_as_float(f2tf32(pb[j].w));
        }
        __syncthreads();
        int kn = k0 + 32;
        if (kn < INCH) {
#pragma unroll
            for (int j = 0; j < 4; j++) {
                int gm = m0 + a_r + 32 * j;
                pa[j] = make_float4(0.f, 0.f, 0.f, 0.f);
                if (gm < NN) pa[j] = *reinterpret_cast<const float4*>(&x[(size_t)gm * INCH + kn + a_c]);
                pb[j] = *reinterpret_cast<const float4*>(&W1[(size_t)(kn + b_r) * C1 + n0 + (b_c0 + 8 * j) * 4]);
            }
        }
#pragma unroll
        for (int ks = 0; ks < 4; ks++) {
            int kk = ks * 8;
            unsigned a[2][4];
#pragma unroll
            for (int mi = 0; mi < 2; mi++) {
                int rb = wm * 32 + mi * 16 + g;
                a[mi][0] = __float_as_uint(As[rb][kk + tg]);
                a[mi][1] = __float_as_uint(As[rb + 8][kk + tg]);
                a[mi][2] = __float_as_uint(As[rb][kk + tg + 4]);
                a[mi][3] = __float_as_uint(As[rb + 8][kk + tg + 4]);
            }
#pragma unroll
            for (int nt = 0; nt < 8; nt++) {
                int col = wn * 64 + nt * 8 + g;
                unsigned b0 = __float_as_uint(Bs[kk + tg][col]);
                unsigned b1 = __float_as_uint(Bs[kk + tg + 4][col]);
                mma_tf32(acc[0][nt], a[0], b0, b1);
                mma_tf32(acc[1][nt], a[1], b0, b1);
            }
        }
        __syncthreads();
    }

    // epilogue: store h1 (bf16) + fused alpha1 partials (fp32)
    float ps[2][2][2] = {}, pd[2][2][2] = {};
#pragma unroll
    for (int mi = 0; mi < 2; mi++) {
        int r = m0 + wm * 32 + mi * 16 + g;
#pragma unroll
        for (int nt = 0; nt < 8; nt++) {
            int c = n0 + wn * 64 + nt * 8 + tg * 2;
            int hl = nt >> 2;
            float w0s = a1s[c], w1s = a1s[c + 1];
            float w0d = a1d[c], w1d = a1d[c + 1];
            if (r < NN) {
                *reinterpret_cast<__nv_bfloat162*>(&g_h1[(size_t)r * C1 + c]) =
                    __floats2bfloat162_rn(acc[mi][nt][0], acc[mi][nt][1]);
            }
            if (r + 8 < NN) {
                *reinterpret_cast<__nv_bfloat162*>(&g_h1[(size_t)(r + 8) * C1 + c]) =
                    __floats2bfloat162_rn(acc[mi][nt][2], acc[mi][nt][3]);
            }
            ps[mi][0][hl] += acc[mi][nt][0] * w0s + acc[mi][nt][1] * w1s;
            ps[mi][1][hl] += acc[mi][nt][2] * w0s + acc[mi][nt][3] * w1s;
            pd[mi][0][hl] += acc[mi][nt][0] * w0d + acc[mi][nt][1] * w1d;
            pd[mi][1][hl] += acc[mi][nt][2] * w0d + acc[mi][nt][3] * w1d;
        }
    }
#pragma unroll
    for (int mi = 0; mi < 2; mi++)
#pragma unroll
        for (int rh = 0; rh < 2; rh++)
#pragma unroll
            for (int hl = 0; hl < 2; hl++) {
                float s = ps[mi][rh][hl], d = pd[mi][rh][hl];
                s += __shfl_xor_sync(~0u, s, 1); s += __shfl_xor_sync(~0u, s, 2);
                d += __shfl_xor_sync(~0u, d, 1); d += __shfl_xor_sync(~0u, d, 2);
                if (tg == 0) {
                    int r = m0 + wm * 32 + mi * 16 + g + rh * 8;
                    if (r < NN) {
                        int head = (n0 >> 5) + wn * 2 + hl;
                        g_as1[r * HEADS + head] = s;
                        g_ad1[r * HEADS + head] = d;
                    }
                }
            }
}

// ---------------- layer1 gather: warp per node (bf16 h1 rows) ----------------
__global__ __launch_bounds__(256) void gather1(const float* __restrict__ b1) {
    int gw = (blockIdx.x * blockDim.x + threadIdx.x) >> 5;
    int l = threadIdx.x & 31;
    int ws = threadIdx.x >> 5;
    __shared__ float sad[8][8];
    __shared__ float sex[8][32 * 9];   // stride 9 -> conflict-free
    if (gw >= NN) return;
    int d = gw;
    int start = g_off[d];
    int deg = g_off[d + 1] - start;

    if (l < HEADS) sad[ws][l] = g_ad1[d * HEADS + l];
    __syncwarp();

    float acc[8];
#pragma unroll
    for (int j = 0; j < 8; j++) acc[j] = 0.f;
    float den = 0.f;
    int h = l >> 2;

    for (int base = 0; base < deg; base += 32) {
        int cnt = min(32, deg - base);
        int s_l = 0;
        if (l < cnt) {
            s_l = g_src[start + base + l];
            const float4* ap = reinterpret_cast<const float4*>(&g_as1[s_l * HEADS]);
            float4 v0 = ap[0];
            float4 v1 = ap[1];
            float* sx = &sex[ws][l * 9];
            sx[0] = lrelu_exp(v0.x + sad[ws][0]);
            sx[1] = lrelu_exp(v0.y + sad[ws][1]);
            sx[2] = lrelu_exp(v0.z + sad[ws][2]);
            sx[3] = lrelu_exp(v0.w + sad[ws][3]);
            sx[4] = lrelu_exp(v1.x + sad[ws][4]);
            sx[5] = lrelu_exp(v1.y + sad[ws][5]);
            sx[6] = lrelu_exp(v1.z + sad[ws][6]);
            sx[7] = lrelu_exp(v1.w + sad[ws][7]);
        }
        __syncwarp();
#pragma unroll 4
        for (int e = 0; e < cnt; e++) {
            int s = __shfl_sync(~0u, s_l, e);
            float ex = sex[ws][e * 9 + h];
            den += ex;
            uint4 rv = *reinterpret_cast<const uint4*>(&g_h1[(size_t)s * C1 + l * 8]);
            float2 f0 = __bfloat1622float2(*reinterpret_cast<__nv_bfloat162*>(&rv.x));
            float2 f1 = __bfloat1622float2(*reinterpret_cast<__nv_bfloat162*>(&rv.y));
            float2 f2 = __bfloat1622float2(*reinterpret_cast<__nv_bfloat162*>(&rv.z));
            float2 f3 = __bfloat1622float2(*reinterpret_cast<__nv_bfloat162*>(&rv.w));
            acc[0] += ex * f0.x; acc[1] += ex * f0.y;
            acc[2] += ex * f1.x; acc[3] += ex * f1.y;
            acc[4] += ex * f2.x; acc[5] += ex * f2.y;
            acc[6] += ex * f3.x; acc[7] += ex * f3.y;
        }
        __syncwarp();
    }

    float inv = 1.f / (den + 1e-16f);
    int chb = l * 8;
    float o[8];
#pragma unroll
    for (int j = 0; j < 8; j++) {
        float v = acc[j] * inv + b1[chb + j];
        o[j] = v > 0.f ? v : expm1f(v);
    }
    float4* dst = reinterpret_cast<float4*>(&g_out1[(size_t)d * C1 + chb]);
    dst[0] = make_float4(o[0], o[1], o[2], o[3]);
    dst[1] = make_float4(o[4], o[5], o[6], o[7]);
}

// ---------------- GEMM2: h2 = out1 @ W2, + fused alpha2 ---------------------
__global__ __launch_bounds__(256) void gemm2_kernel(const float* __restrict__ W2,
                                                    const float* __restrict__ a2s,
                                                    const float* __restrict__ a2d) {
    __shared__ float As[128][36];
    __shared__ float Bs[32][44];
    int tid = threadIdx.x;
    int lane = tid & 31, wid = tid >> 5;
    int g = lane >> 2, tg = lane & 3;
    int m0 = blockIdx.x * 128;

    float acc[5][4];
#pragma unroll
    for (int j = 0; j < 5; j++)
#pragma unroll
        for (int k = 0; k < 4; k++) acc[j][k] = 0.f;

    int a_r = tid >> 3;
    int a_c = (tid & 7) * 4;

    for (int k0 = 0; k0 < C1; k0 += 32) {
#pragma unroll
        for (int j = 0; j < 4; j++) {
            int r = a_r + 32 * j;
            int gm = m0 + r;
            float4 v = make_float4(0.f, 0.f, 0.f, 0.f);
            if (gm < NN) v = *reinterpret_cast<const float4*>(&g_out1[(size_t)gm * C1 + k0 + a_c]);
            As[r][a_c + 0] = __uint_as_float(f2tf32(v.x));
            As[r][a_c + 1] = __uint_as_float(f2tf32(v.y));
            As[r][a_c + 2] = __uint_as_float(f2tf32(v.z));
            As[r][a_c + 3] = __uint_as_float(f2tf32(v.w));
        }
        for (int idx = tid; idx < 32 * OUTC; idx += 256) {
            int r = idx / OUTC, c = idx % OUTC;
            Bs[r][c] = __uint_as_float(f2tf32(W2[(size_t)(k0 + r) * OUTC + c]));
        }
        __syncthreads();
#pragma unroll
        for (int ks = 0; ks < 4; ks++) {
            int kk = ks * 8;
            unsigned a[4];
            int rb = wid * 16 + g;
            a[0] = __float_as_uint(As[rb][kk + tg]);
            a[1] = __float_as_uint(As[rb + 8][kk + tg]);
            a[2] = __float_as_uint(As[rb][kk + tg + 4]);
            a[3] = __float_as_uint(As[rb + 8][kk + tg + 4]);
#pragma unroll
            for (int nt = 0; nt < 5; nt++) {
                int col = nt * 8 + g;
                unsigned b0 = __float_as_uint(Bs[kk + tg][col]);
                unsigned b1r = __float_as_uint(Bs[kk + tg + 4][col]);
                mma_tf32(acc[nt], a, b0, b1r);
            }
        }
        __syncthreads();
    }
    int rlo = m0 + wid * 16 + g;
    int rhi = rlo + 8;
    float s_lo = 0.f, s_hi = 0.f, d_lo = 0.f, d_hi = 0.f;
#pragma unroll
    for (int nt = 0; nt < 5; nt++) {
        int c = nt * 8 + tg * 2;
        float w0s = a2s[c], w1s = a2s[c + 1];
        float w0d = a2d[c], w1d = a2d[c + 1];
        if (rlo < NN) {
            g_h2[(size_t)rlo * OUTC + c]     = acc[nt][0];
            g_h2[(size_t)rlo * OUTC + c + 1] = acc[nt][1];
        }
        if (rhi < NN) {
            g_h2[(size_t)rhi * OUTC + c]     = acc[nt][2];
            g_h2[(size_t)rhi * OUTC + c + 1] = acc[nt][3];
        }
        s_lo += acc[nt][0] * w0s + acc[nt][1] * w1s;
        s_hi += acc[nt][2] * w0s + acc[nt][3] * w1s;
        d_lo += acc[nt][0] * w0d + acc[nt][1] * w1d;
        d_hi += acc[nt][2] * w0d + acc[nt][3] * w1d;
    }
#pragma unroll
    for (int o = 1; o <= 2; o <<= 1) {
        s_lo += __shfl_xor_sync(~0u, s_lo, o);
        s_hi += __shfl_xor_sync(~0u, s_hi, o);
        d_lo += __shfl_xor_sync(~0u, d_lo, o);
        d_hi += __shfl_xor_sync(~0u, d_hi, o);
    }
    if (tg == 0) {
        if (rlo < NN) { g_as2[rlo] = s_lo; g_ad2[rlo] = d_lo; }
        if (rhi < NN) { g_as2[rhi] = s_hi; g_ad2[rhi] = d_hi; }
    }
}

// ---------------- layer2 gather: warp per node, fused log_softmax ------------
__global__ __launch_bounds__(256) void gather2(const float* __restrict__ b2,
                                               float* __restrict__ out) {
    int gw = (blockIdx.x * blockDim.x + threadIdx.x) >> 5;
    int l = threadIdx.x & 31;
    if (gw >= NN) return;
    int d = gw;
    int start = g_off[d];
    int deg = g_off[d + 1] - start;

    float ad = g_ad2[d];
    float acc0 = 0.f, acc1 = 0.f, denp = 0.f;

    for (int base = 0; base < deg; base += 32) {
        int cnt = min(32, deg - base);
        int s_l = 0;
        float ex_l = 0.f;
        if (l < cnt) {
            s_l = g_src[start + base + l];
            ex_l = lrelu_exp(g_as2[s_l] + ad);
        }
        denp += ex_l;
#pragma unroll 4
        for (int e = 0; e < cnt; e++) {
            int s = __shfl_sync(~0u, s_l, e);
            float ex = __shfl_sync(~0u, ex_l, e);
            acc0 += ex * g_h2[(size_t)s * OUTC + l];
            if (l < 8) acc1 += ex * g_h2[(size_t)s * OUTC + 32 + l];
        }
    }
    float den = denp;
#pragma unroll
    for (int o = 16; o; o >>= 1) den += __shfl_xor_sync(~0u, den, o);
    float inv = 1.f / (den + 1e-16f);

    float v1 = acc0 * inv + b2[l];
    float v2 = (l < 8) ? (acc1 * inv + b2[32 + l]) : -1e30f;
    float m = fmaxf(v1, v2);
#pragma unroll
    for (int o = 16; o; o >>= 1) m = fmaxf(m, __shfl_xor_sync(~0u, m, o));
    float sum = __expf(v1 - m) + ((l < 8) ? __expf(v2 - m) : 0.f);
#pragma unroll
    for (int o = 16; o; o >>= 1) sum += __shfl_xor_sync(~0u, sum, o);
    float lse = m + logf(sum);
    out[(size_t)d * OUTC + l] = v1 - lse;
    if (l < 8) out[(size_t)d * OUTC + 32 + l] = v2 - lse;
}

// ---------------- launch --------------------------------------------------------
extern "C" void kernel_launch(void* const* d_in, const int* in_sizes, int n_in,
                              void* d_out, int out_size) {
    const float* x   = (const float*)d_in[0];
    const int*   ei  = (const int*)d_in[1];
    const float* W1  = (const float*)d_in[2];
    const float* a1s = (const float*)d_in[3];
    const float* a1d = (const float*)d_in[4];
    const float* b1  = (const float*)d_in[5];
    const float* W2  = (const float*)d_in[6];
    const float* a2s = (const float*)d_in[7];
    const float* a2d = (const float*)d_in[8];
    const float* b2  = (const float*)d_in[9];
    float*       out = (float*)d_out;

    init_deg<<<(NN + 255) / 256, 256>>>();
    deg_hist<<<(E0 + 255) / 256, 256>>>(ei);
    scan_kernel<<<1, 1024>>>();
    fill_csr<<<(E0 + 255) / 256, 256>>>(ei);

    gemm1_kernel<<<dim3(2, (NN + 127) / 128), 256>>>(x, W1, a1s, a1d);

    gather1<<<(NN * 32 + 255) / 256, 256>>>(b1);

    gemm2_kernel<<<(NN + 127) / 128, 256>>>(W2, a2s, a2d);

    gather2<<<(NN * 32 + 255) / 256, 256>>>(b2, out);
}